// round 14
// baseline (speedup 1.0000x reference)
#include <cuda_runtime.h>
#include <cuda_fp16.h>
#include <math.h>
#include <cstdint>

// Problem constants
#define NN    4096
#define HDIM  32
#define TROLL 200
#define FIN   5

#define NCTA   128             // persistent grid; CTA bid owns nodes [bid*32, bid*32+32)
#define NKT2   32              // k-tiles per step (full K=4096)

// fp16 scaling: A stored x4096 (avoids subnormals); B (h,c) stored x256.
#define A_SCALE   4096.0f
#define B_SCALE   256.0f
#define AB_INV    (1.0f / (4096.0f * 256.0f))
#define A_INV     (1.0f / 4096.0f)

typedef unsigned long long u64;

// ---------------- fp32x2 / mma helpers ---------------------------------------
__device__ __forceinline__ u64 pack2(float x, float y) {
    u64 r; asm("mov.b64 %0, {%1, %2};" : "=l"(r) : "f"(x), "f"(y)); return r;
}
__device__ __forceinline__ void unpack2(u64 v, float& x, float& y) {
    asm("mov.b64 {%0, %1}, %2;" : "=f"(x), "=f"(y) : "l"(v));
}
__device__ __forceinline__ void ffma2(u64& d, u64 a, u64 b) {
    asm("fma.rn.f32x2 %0, %1, %2, %0;" : "+l"(d) : "l"(a), "l"(b));
}
__device__ __forceinline__ uint32_t smem_u32(const void* p) {
    uint32_t a;
    asm("{ .reg .u64 t; cvta.to.shared.u64 t, %1; cvt.u32.u64 %0, t; }" : "=r"(a) : "l"(p));
    return a;
}
__device__ __forceinline__ void ldm_x4(uint32_t* r, uint32_t addr) {
    asm volatile("ldmatrix.sync.aligned.m8n8.x4.shared.b16 {%0,%1,%2,%3}, [%4];"
        : "=r"(r[0]), "=r"(r[1]), "=r"(r[2]), "=r"(r[3]) : "r"(addr));
}
__device__ __forceinline__ void mma_f16(float* d, const uint32_t* a, uint32_t b0, uint32_t b1) {
    asm volatile("mma.sync.aligned.m16n8k16.row.col.f32.f16.f16.f32 "
        "{%0,%1,%2,%3}, {%4,%5,%6,%7}, {%8,%9}, {%0,%1,%2,%3};"
        : "+f"(d[0]), "+f"(d[1]), "+f"(d[2]), "+f"(d[3])
        : "r"(a[0]), "r"(a[1]), "r"(a[2]), "r"(a[3]), "r"(b0), "r"(b1));
}
__device__ __forceinline__ void cp_async16(uint32_t saddr, const void* gaddr) {
    asm volatile("cp.async.cg.shared.global [%0], [%1], 16;"
        :: "r"(saddr), "l"(gaddr) : "memory");
}
#define CP_COMMIT() asm volatile("cp.async.commit_group;" ::: "memory")

// ---------------- device scratch ---------------------------------------------
__device__ __align__(16) float g_C1[(size_t)NN * 1024];            // A @ Xr (fp32)
__device__ __align__(16) float g_U[101 * 128];
__device__ __align__(16) float g_bias[128];
__device__ __align__(16) float g_U4[13056];                        // [(k*32+l)*4+q]=U[k][l+32q]; +bias4
__device__ __align__(128) unsigned g_ctrs[256];                    // spread barrier counters ([i*32], i<8)
// A (x4096) fp16, ldmatrix-ready 32x128 tiles (8KB).
// tile (rt, ktg) at ((rt*32+ktg) << 13); byte(rin,k)=rin*256+(((k>>3)^(rin&7))<<4)+(k&7)*2
__device__ __align__(16) __half g_Ah[(size_t)NN * NN];
// HC^T (x256) fp16, 64x128 tiles (16KB), tile ktg at (ktg<<14)
__device__ __align__(16) __half g_Bh[(size_t)64 * NN];
// Xr^T fp16, 64x128 tiles, tile (ktg,nt) at ((nt*32+ktg)<<14)
__device__ __align__(16) __half g_XBh[(size_t)1024 * NN];

// ---------------- setup: fused gate matrix U + repacked U4 -------------------
__global__ void setup_kernel(const float* __restrict__ Wx, const float* __restrict__ Wh,
                             const float* __restrict__ Wc, const float* __restrict__ W_ih,
                             const float* __restrict__ W_hh, const float* __restrict__ b_ih,
                             const float* __restrict__ b_hh) {
    const int j = threadIdx.x;
    __shared__ float sWih[128 * 32];
    for (int i = j; i < 128 * 32; i += 128) sWih[i] = W_ih[i];
    __syncthreads();
    for (int r = 0; r < 32; r++) {
        float s = 0.f;
        for (int m = 0; m < 32; m++) s += Wh[r * 32 + m] * sWih[j * 32 + m];
        g_U[r * 128 + j] = s;
    }
    for (int r = 0; r < 32; r++) {
        float s = 0.f;
        for (int m = 0; m < 32; m++) s += Wc[r * 32 + m] * sWih[j * 32 + m];
        g_U[(32 + r) * 128 + j] = s;
    }
    for (int m = 0; m < 32; m++) g_U[(64 + m) * 128 + j] = W_hh[j * 32 + m];
    for (int f = 0; f < FIN; f++) {
        float s = 0.f;
        for (int m = 0; m < 32; m++) s += Wx[f * 32 + m] * sWih[j * 32 + m];
        g_U[(96 + f) * 128 + j] = s;
    }
    g_bias[j] = b_ih[j] + b_hh[j];
    __syncthreads();
    {
        const int l = j & 31, q = j >> 5;
        for (int k = 0; k < 101; k++)
            g_U4[(k * 32 + l) * 4 + q] = g_U[k * 128 + l + 32 * q];
        g_U4[(101 * 32 + l) * 4 + q] = g_bias[l + 32 * q];
    }
}

// Zero B tiles + barrier counters (graph-replay determinism).
__global__ void zero_state_kernel() {
    int i = blockIdx.x * blockDim.x + threadIdx.x;   // 262144 threads
    g_Bh[i] = __float2half(0.f);
    if (i < 256) g_ctrs[i] = 0u;
}

// ---------------- A -> fp16 (x4096) 32-row ldmatrix tiles (once) --------------
__global__ void aconv_kernel(const float* __restrict__ A) {
    int idx = blockIdx.x * blockDim.x + threadIdx.x;
    int r = idx >> 9;
    int k = (idx & 511) << 3;
    int rt = r >> 5, rin = r & 31;
    int ktg = k >> 7, kin = k & 127;
    uint32_t byte = (uint32_t)(rin * 256 + ((((kin >> 3)) ^ (rin & 7)) << 4));
    size_t tile = ((size_t)(rt * 32 + ktg)) << 13;     // 8KB tiles
    unsigned short h[8];
    #pragma unroll
    for (int i = 0; i < 8; i++) {
        float x = A[(size_t)r * NN + k + i] * A_SCALE;
        h[i] = __half_as_ushort(__float2half(x));
    }
    uint4 vh = make_uint4((uint32_t)h[0] | ((uint32_t)h[1] << 16),
                          (uint32_t)h[2] | ((uint32_t)h[3] << 16),
                          (uint32_t)h[4] | ((uint32_t)h[5] << 16),
                          (uint32_t)h[6] | ((uint32_t)h[7] << 16));
    *reinterpret_cast<uint4*>(reinterpret_cast<char*>(g_Ah) + tile + byte) = vh;
}

// ---------------- X -> Xr^T fp16 ldmatrix tiles (once) ------------------------
__global__ void xrconv_kernel(const float* __restrict__ X) {
    int idx = blockIdx.x * blockDim.x + threadIdx.x;
    int q  = idx >> 9;
    int kk = (idx & 511) << 3;
    int nt = q >> 6, rown = q & 63;
    int ktg = kk >> 7, kin = kk & 127;
    uint32_t byte = (uint32_t)(rown * 256 + ((((kin >> 3)) ^ (rown & 7)) << 4));
    size_t tile = ((size_t)(nt * 32 + ktg)) << 14;
    const bool valid = (q < TROLL * FIN);
    const int t = q / FIN, f = q - t * FIN;
    unsigned short h[8];
    #pragma unroll
    for (int i = 0; i < 8; i++) {
        float x = valid ? X[((size_t)t * NN + kk + i) * FIN + f] : 0.f;
        h[i] = __half_as_ushort(__float2half(x));
    }
    uint4 vh = make_uint4((uint32_t)h[0] | ((uint32_t)h[1] << 16),
                          (uint32_t)h[2] | ((uint32_t)h[3] << 16),
                          (uint32_t)h[4] | ((uint32_t)h[5] << 16),
                          (uint32_t)h[6] | ((uint32_t)h[7] << 16));
    *reinterpret_cast<uint4*>(reinterpret_cast<char*>(g_XBh) + tile + byte) = vh;
}

// ---------------- C1 SMEM layout (M=128 tiles, A = 4 sub-tiles) ----------------
#define C1_STG  49152          // A 32K (4 x 8K sub-tiles) | B 16K
#define C1_SMB  32768
#define C1_SMEM (2 * C1_STG)

// ---------------- C1 = A @ Xr via single fp16 mma (one-time) -------------------
__global__ void __launch_bounds__(256, 1) c1_mma() {
    extern __shared__ __align__(16) char smem[];
    const int tid  = threadIdx.x;
    const int lane = tid & 31;
    const int wid  = tid >> 5;
    const int wm   = wid & 3;
    const int wn   = wid >> 2;
    const int mt   = blockIdx.x;
    const int nt   = blockIdx.y;
    const uint32_t sbase = smem_u32(smem);

    auto load_tile = [&](int kt, int b) {
        const uint32_t s = sbase + b * C1_STG;
        #pragma unroll
        for (int q = 0; q < 4; q++) {
            const char* gAq = reinterpret_cast<const char*>(g_Ah)
                            + (((size_t)((mt * 4 + q) * 32 + kt)) << 13);
            #pragma unroll
            for (int i = 0; i < 2; i++)
                cp_async16(s + q * 8192 + (tid + i * 256) * 16, gAq + (tid + i * 256) * 16);
        }
        const char* gB = reinterpret_cast<const char*>(g_XBh) + (((size_t)(nt * 32 + kt)) << 14);
        #pragma unroll
        for (int i = 0; i < 4; i++)
            cp_async16(s + C1_SMB + (tid + i * 256) * 16, gB + (tid + i * 256) * 16);
        CP_COMMIT();
    };

    float acc[2][4][4];
    #pragma unroll
    for (int im = 0; im < 2; im++)
        #pragma unroll
        for (int jn = 0; jn < 4; jn++)
            #pragma unroll
            for (int q = 0; q < 4; q++) acc[im][jn][q] = 0.f;

    load_tile(0, 0);
    load_tile(1, 1);

    const int arow[2] = { wm * 32 + (lane & 15), wm * 32 + 16 + (lane & 15) };
    const int acolh   = (lane >> 4);
    const int nrow[2] = { wn * 32 + (lane & 7) + ((lane >> 4) << 3),
                          wn * 32 + 16 + (lane & 7) + ((lane >> 4) << 3) };
    const int bcolh   = (lane >> 3) & 1;

    for (int kt = 0; kt < 32; kt++) {
        const int b = kt & 1;
        if (kt == 31) asm volatile("cp.async.wait_group 0;" ::: "memory");
        else          asm volatile("cp.async.wait_group 1;" ::: "memory");
        __syncthreads();

        const uint32_t sA = sbase + b * C1_STG;
        const uint32_t sB = sA + C1_SMB;

        #pragma unroll
        for (int ks = 0; ks < 8; ks++) {
            const int ck = ks * 2;
            uint32_t ah[2][4], bh[2][4];
            #pragma unroll
            for (int im = 0; im < 2; im++) {
                const int r = arow[im];
                const uint32_t off = (uint32_t)((r >> 5) * 8192 + (r & 31) * 256
                                   + (((ck + acolh) ^ (r & 7)) << 4));
                ldm_x4(ah[im], sA + off);
            }
            #pragma unroll
            for (int g = 0; g < 2; g++) {
                const int r = nrow[g];
                ldm_x4(bh[g], sB + (uint32_t)(r * 256 + (((ck + bcolh) ^ (r & 7)) << 4)));
            }
            #pragma unroll
            for (int im = 0; im < 2; im++)
                #pragma unroll
                for (int jn = 0; jn < 4; jn++) {
                    const int g = jn >> 1, w = (jn & 1) * 2;
                    mma_f16(acc[im][jn], ah[im], bh[g][w], bh[g][w + 1]);
                }
        }
        __syncthreads();
        if (kt + 2 < 32) load_tile(kt + 2, b);
    }

    const int row0 = mt * 128 + wm * 32 + (lane >> 2);
    const int col0 = nt * 64 + wn * 32 + (lane & 3) * 2;
    #pragma unroll
    for (int im = 0; im < 2; im++)
        #pragma unroll
        for (int jn = 0; jn < 4; jn++) {
            const int r = row0 + im * 16;
            const int c = col0 + jn * 8;
            *reinterpret_cast<float2*>(&g_C1[(size_t)r * 1024 + c]) =
                make_float2(acc[im][jn][0] * A_INV, acc[im][jn][1] * A_INV);
            *reinterpret_cast<float2*>(&g_C1[(size_t)(r + 8) * 1024 + c]) =
                make_float2(acc[im][jn][2] * A_INV, acc[im][jn][3] * A_INV);
        }
}

// ---------------- spread-counter grid barrier ----------------------------------
// 8 counters, 16 CTAs each (parallel arrivals); 8 threads poll in parallel.
__device__ __forceinline__ void grid_sync(unsigned q) {
    __syncthreads();
    if (threadIdx.x == 0) {
        __threadfence();
        atomicAdd(&g_ctrs[(blockIdx.x & 7) * 32], 1u);
    }
    if (threadIdx.x < 8) {
        const unsigned goal = q * 16u;
        unsigned v;
        do {
            asm volatile("ld.acquire.gpu.global.u32 %0, [%1];"
                         : "=r"(v) : "l"(&g_ctrs[threadIdx.x * 32]) : "memory");
        } while (v < goal);
    }
    __syncthreads();
}

// ---------------- fused SMEM layout --------------------------------------------
#define STG2    24576         // stage: A 8K | B 16K
#define SM_B2   8192
#define U_OFF   (4 * STG2)               // 98304: persistent U4 (52224 B)
#define MACC_OFF (U_OFF + 52224)         // 150528: Macc 32x64 f32 (8192 B)
#define SHC_OFF  (MACC_OFF + 8192)       // 158720: h/c state 32x64 f32 (8192 B)
#define SFC_OFF  (SHC_OFF + 8192)        // 166912: per-warp C1 scratch (256 B)
#define FS_SMEM  (SFC_OFF + 256)         // 167168 total

// ---------------- persistent fused step loop -----------------------------------
// 128 CTAs x 256 thr; CTA owns 32 nodes: full-K mma (M=32,N=64,K=4096) -> gates
// in SMEM -> B-tile writes -> ONE grid barrier. HC state lives in SMEM.
__global__ void __launch_bounds__(256, 1) fused_steps(const float* __restrict__ W_fc,
                                                      const float* __restrict__ b_fc,
                                                      float* __restrict__ out) {
    extern __shared__ __align__(16) char smem[];
    const int tid  = threadIdx.x;
    const int lane = tid & 31;
    const int wid  = tid >> 5;
    const int wm   = wid & 1;          // m half (16 rows)
    const int wn   = wid >> 1;         // n quarter (16 cols)
    const int bid  = blockIdx.x;
    const uint32_t sbase = smem_u32(smem);

    // persistent U table + zero local HC state
    float4* Us4 = reinterpret_cast<float4*>(smem + U_OFF);
    {
        const float4* gU4 = reinterpret_cast<const float4*>(g_U4);
        for (int i = tid; i < 3264; i += 256) Us4[i] = gU4[i];
        float* sHC0 = reinterpret_cast<float*>(smem + SHC_OFF);
        for (int i = tid; i < 2048; i += 256) sHC0[i] = 0.f;
    }
    float* Macc = reinterpret_cast<float*>(smem + MACC_OFF);
    float* sHC  = reinterpret_cast<float*>(smem + SHC_OFF);
    float* sfc  = reinterpret_cast<float*>(smem + SFC_OFF);
    __syncthreads();

    auto issueA = [&](int kt) {               // A tile (bid, kt) -> stage kt&3 (8KB)
        const char* gA = reinterpret_cast<const char*>(g_Ah)
                       + (((size_t)(bid * 32 + kt)) << 13);
        const uint32_t d = sbase + (kt & 3) * STG2;
        #pragma unroll
        for (int i = 0; i < 2; i++)
            cp_async16(d + (tid + i * 256) * 16, gA + (tid + i * 256) * 16);
    };
    auto issueB = [&](int kt) {               // B tile kt -> stage kt&3 + SM_B2 (16KB)
        const char* gB = reinterpret_cast<const char*>(g_Bh) + ((size_t)kt << 14);
        const uint32_t d = sbase + (kt & 3) * STG2 + SM_B2;
        #pragma unroll
        for (int i = 0; i < 4; i++)
            cp_async16(d + (tid + i * 256) * 16, gB + (tid + i * 256) * 16);
    };

    const int arow  = wm * 16 + (lane & 15);
    const int acolh = lane >> 4;
    const int brow  = wn * 16 + (lane & 7) + ((lane >> 4) << 3);
    const int bcolh = (lane >> 3) & 1;

    // prologue: A tiles 0..3 (4 groups)
    issueA(0); CP_COMMIT();
    issueA(1); CP_COMMIT();
    issueA(2); CP_COMMIT();
    issueA(3); CP_COMMIT();

    unsigned q = 0;

    for (int t = 0; t < TROLL; t++) {
        // B tiles 0..3 (4 groups) — after barrier, gates output visible
        issueB(0); CP_COMMIT();
        issueB(1); CP_COMMIT();
        issueB(2); CP_COMMIT();
        issueB(3); CP_COMMIT();

        float acc[2][4];
        #pragma unroll
        for (int jn = 0; jn < 2; jn++)
            #pragma unroll
            for (int p = 0; p < 4; p++) acc[jn][p] = 0.f;

        #pragma unroll 4
        for (int kt = 0; kt < NKT2; kt++) {
            asm volatile("cp.async.wait_group 3;" ::: "memory");
            __syncthreads();

            const uint32_t sA = sbase + (kt & 3) * STG2;
            const uint32_t sB = sA + SM_B2;

            #pragma unroll
            for (int ks = 0; ks < 8; ks++) {
                const int ck = ks * 2;
                uint32_t ah[4], bh[4];
                ldm_x4(ah, sA + (uint32_t)(arow * 256 + (((ck + acolh) ^ (arow & 7)) << 4)));
                ldm_x4(bh, sB + (uint32_t)(brow * 256 + (((ck + bcolh) ^ (brow & 7)) << 4)));
                mma_f16(acc[0], ah, bh[0], bh[1]);
                mma_f16(acc[1], ah, bh[2], bh[3]);
            }
            __syncthreads();

            if (kt + 4 < NKT2) { issueA(kt + 4); issueB(kt + 4); CP_COMMIT(); }
            else               { issueA(kt - 28); CP_COMMIT(); }   // next-step A prefetch
        }

        // ---- epilogue: acc -> Macc (SMEM) ----
        {
            const int r0 = wm * 16 + (lane >> 2);
            const int c0 = wn * 16 + (lane & 3) * 2;
            #pragma unroll
            for (int jn = 0; jn < 2; jn++) {
                *reinterpret_cast<float2*>(&Macc[r0 * 64 + c0 + jn * 8]) =
                    make_float2(acc[jn][0] * AB_INV, acc[jn][1] * AB_INV);
                *reinterpret_cast<float2*>(&Macc[(r0 + 8) * 64 + c0 + jn * 8]) =
                    make_float2(acc[jn][2] * AB_INV, acc[jn][3] * AB_INV);
            }
        }
        __syncthreads();

        // ---- gates: each warp handles 4 of this CTA's 32 nodes ----
        {
            const float4 bb = Us4[3232 + lane];
            #pragma unroll
            for (int it = 0; it < 4; it++) {
                const int nloc = wid * 4 + it;
                const int n = bid * 32 + nloc;
                if (lane < FIN) sfc[wid * 8 + lane] = g_C1[(size_t)n * 1024 + t * FIN + lane];
                __syncwarp();

                u64 a01 = pack2(bb.x, bb.y);
                u64 a23 = pack2(bb.z, bb.w);
                #pragma unroll
                for (int k = 0; k < 101; k++) {
                    const float s = (k < 64) ? Macc[nloc * 64 + k]
                                  : (k < 96) ? sHC[nloc * 64 + (k - 64)]
                                             : sfc[wid * 8 + (k - 96)];
                    const u64 ss = pack2(s, s);
                    const float4 u4 = Us4[k * 32 + lane];
                    ffma2(a01, pack2(u4.x, u4.y), ss);
                    ffma2(a23, pack2(u4.z, u4.w), ss);
                }
                float gi, gf, gg, go;
                unpack2(a01, gi, gf);
                unpack2(a23, gg, go);

                const float ii = 1.f / (1.f + expf(-gi));
                const float ff = 1.f / (1.f + expf(-gf));
                const float g3 = tanhf(gg);
                const float oo = 1.f / (1.f + expf(-go));
                const float c_old = sHC[nloc * 64 + 32 + lane];
                const float c_new = ff * c_old + ii * g3;
                const float h_new = oo * tanhf(c_new);
                sHC[nloc * 64 + lane]      = h_new;
                sHC[nloc * 64 + 32 + lane] = c_new;

                // B-tile writes (fp16, x256; tile ktg = n>>7 at ktg<<14)
                const int ktg = n >> 7, kin = n & 127;
                const size_t tbase = (size_t)ktg << 14;
                const uint32_t kpart = (uint32_t)(((kin >> 3) & 0xF) << 4);
                const uint32_t klow  = (uint32_t)((kin & 7) * 2);
                char* const pB = reinterpret_cast<char*>(g_Bh) + tbase;

                const __half hh = __float2half(h_new * B_SCALE);
                const __half ch = __float2half(c_new * B_SCALE);

                const uint32_t bh_row = (uint32_t)lane;
                const uint32_t bc_row = (uint32_t)(lane + 32);
                const uint32_t offh = bh_row * 256 + (kpart ^ ((bh_row & 7) << 4)) + klow;
                const uint32_t offc = bc_row * 256 + (kpart ^ ((bc_row & 7) << 4)) + klow;
                *reinterpret_cast<__half*>(pB + offh) = hh;
                *reinterpret_cast<__half*>(pB + offc) = ch;
                __syncwarp();
            }
        }

        grid_sync(++q);   // single barrier per step
    }

    asm volatile("cp.async.wait_group 0;" ::: "memory");

    // ---- final projection for own nodes (h in SMEM) ----
    if (tid < 32) {
        float s = b_fc[0];
        #pragma unroll
        for (int u = 0; u < HDIM; u++) s += sHC[tid * 64 + u] * W_fc[u];
        out[bid * 32 + tid] = s;
    }
}

// ---------------- launch --------------------------------------------------------
extern "C" void kernel_launch(void* const* d_in, const int* in_sizes, int n_in,
                              void* d_out, int out_size) {
    const float* X    = (const float*)d_in[0];
    const float* A    = (const float*)d_in[1];
    const float* Wx   = (const float*)d_in[2];
    const float* Wh   = (const float*)d_in[3];
    const float* Wc   = (const float*)d_in[4];
    const float* W_ih = (const float*)d_in[5];
    const float* W_hh = (const float*)d_in[6];
    const float* b_ih = (const float*)d_in[7];
    const float* b_hh = (const float*)d_in[8];
    const float* W_fc = (const float*)d_in[9];
    const float* b_fc = (const float*)d_in[10];

    cudaFuncSetAttribute(c1_mma, cudaFuncAttributeMaxDynamicSharedMemorySize, C1_SMEM);
    cudaFuncSetAttribute(fused_steps, cudaFuncAttributeMaxDynamicSharedMemorySize, FS_SMEM);

    setup_kernel<<<1, 128>>>(Wx, Wh, Wc, W_ih, W_hh, b_ih, b_hh);
    zero_state_kernel<<<1024, 256>>>();
    xrconv_kernel<<<(1024 * 512) / 256, 256>>>(X);
    aconv_kernel<<<(NN * 512) / 256, 256>>>(A);
    c1_mma<<<dim3(32, 16), 256, C1_SMEM>>>();
    fused_steps<<<NCTA, 256, FS_SMEM>>>(W_fc, b_fc, (float*)d_out);
}

// round 15
// speedup vs baseline: 1.1927x; 1.1927x over previous
#include <cuda_runtime.h>
#include <cuda_fp16.h>
#include <math.h>
#include <cstdint>

// Problem constants
#define NN    4096
#define HDIM  32
#define TROLL 200
#define FIN   5

#define MSPLIT 4               // K-split for step GEMM; each CTA does K=1024
#define NKT    8               // k-tiles per step CTA
#define NCTA   128             // persistent grid size (mt*4 + z)

// fp16 scaling: A stored x4096 (avoids subnormals); B (h,c) stored x256.
#define A_SCALE   4096.0f
#define B_SCALE   256.0f
#define AB_INV    (1.0f / (4096.0f * 256.0f))
#define A_INV     (1.0f / 4096.0f)

typedef unsigned long long u64;

// ---------------- fp32x2 / mma helpers ---------------------------------------
__device__ __forceinline__ u64 pack2(float x, float y) {
    u64 r; asm("mov.b64 %0, {%1, %2};" : "=l"(r) : "f"(x), "f"(y)); return r;
}
__device__ __forceinline__ void unpack2(u64 v, float& x, float& y) {
    asm("mov.b64 {%0, %1}, %2;" : "=f"(x), "=f"(y) : "l"(v));
}
__device__ __forceinline__ void ffma2(u64& d, u64 a, u64 b) {
    asm("fma.rn.f32x2 %0, %1, %2, %0;" : "+l"(d) : "l"(a), "l"(b));
}
__device__ __forceinline__ uint32_t smem_u32(const void* p) {
    uint32_t a;
    asm("{ .reg .u64 t; cvta.to.shared.u64 t, %1; cvt.u32.u64 %0, t; }" : "=r"(a) : "l"(p));
    return a;
}
__device__ __forceinline__ void ldm_x4(uint32_t* r, uint32_t addr) {
    asm volatile("ldmatrix.sync.aligned.m8n8.x4.shared.b16 {%0,%1,%2,%3}, [%4];"
        : "=r"(r[0]), "=r"(r[1]), "=r"(r[2]), "=r"(r[3]) : "r"(addr));
}
__device__ __forceinline__ void mma_f16(float* d, const uint32_t* a, uint32_t b0, uint32_t b1) {
    asm volatile("mma.sync.aligned.m16n8k16.row.col.f32.f16.f16.f32 "
        "{%0,%1,%2,%3}, {%4,%5,%6,%7}, {%8,%9}, {%0,%1,%2,%3};"
        : "+f"(d[0]), "+f"(d[1]), "+f"(d[2]), "+f"(d[3])
        : "r"(a[0]), "r"(a[1]), "r"(a[2]), "r"(a[3]), "r"(b0), "r"(b1));
}
__device__ __forceinline__ void cp_async16(uint32_t saddr, const void* gaddr) {
    asm volatile("cp.async.cg.shared.global [%0], [%1], 16;"
        :: "r"(saddr), "l"(gaddr) : "memory");
}
#define CP_COMMIT() asm volatile("cp.async.commit_group;" ::: "memory")

// ---------------- device scratch ---------------------------------------------
__device__ __align__(16) float g_HC[NN * 64];                      // [n][0:32]=h,[32:64]=c
__device__ __align__(16) float g_Mpart[(size_t)MSPLIT * NN * 64];  // K-split partials
__device__ __align__(16) float g_C1[(size_t)NN * 1024];            // A @ Xr (fp32)
__device__ __align__(16) float g_U[101 * 128];
__device__ __align__(16) float g_bias[128];
__device__ __align__(16) float g_U4[13056];                        // [(k*32+l)*4+q]=U[k][l+32q]; +bias4
__device__ __align__(128) unsigned g_ctrs[256];                    // spread barrier counters ([i*32], i<8)
// A (x4096) fp16, ldmatrix-ready 128x128 tiles.
// tile (mt, ktg) at ((mt*32+ktg) << 15); byte(row,k)=row*256+(((k>>3)^(row&7))<<4)+(k&7)*2
__device__ __align__(16) __half g_Ah[(size_t)NN * NN];
// HC^T (x256) fp16, 64x128 tiles (16KB), tile ktg at (ktg<<14)
__device__ __align__(16) __half g_Bh[(size_t)64 * NN];
// Xr^T fp16, 64x128 tiles, tile (ktg,nt) at ((nt*32+ktg)<<14)
__device__ __align__(16) __half g_XBh[(size_t)1024 * NN];

// ---------------- setup: fused gate matrix U + repacked U4 -------------------
__global__ void setup_kernel(const float* __restrict__ Wx, const float* __restrict__ Wh,
                             const float* __restrict__ Wc, const float* __restrict__ W_ih,
                             const float* __restrict__ W_hh, const float* __restrict__ b_ih,
                             const float* __restrict__ b_hh) {
    const int j = threadIdx.x;
    __shared__ float sWih[128 * 32];
    for (int i = j; i < 128 * 32; i += 128) sWih[i] = W_ih[i];
    __syncthreads();
    for (int r = 0; r < 32; r++) {
        float s = 0.f;
        for (int m = 0; m < 32; m++) s += Wh[r * 32 + m] * sWih[j * 32 + m];
        g_U[r * 128 + j] = s;
    }
    for (int r = 0; r < 32; r++) {
        float s = 0.f;
        for (int m = 0; m < 32; m++) s += Wc[r * 32 + m] * sWih[j * 32 + m];
        g_U[(32 + r) * 128 + j] = s;
    }
    for (int m = 0; m < 32; m++) g_U[(64 + m) * 128 + j] = W_hh[j * 32 + m];
    for (int f = 0; f < FIN; f++) {
        float s = 0.f;
        for (int m = 0; m < 32; m++) s += Wx[f * 32 + m] * sWih[j * 32 + m];
        g_U[(96 + f) * 128 + j] = s;
    }
    g_bias[j] = b_ih[j] + b_hh[j];
    __syncthreads();
    {
        const int l = j & 31, q = j >> 5;
        for (int k = 0; k < 101; k++)
            g_U4[(k * 32 + l) * 4 + q] = g_U[k * 128 + l + 32 * q];
        g_U4[(101 * 32 + l) * 4 + q] = g_bias[l + 32 * q];
    }
}

// Zero h/c, B tiles, and barrier counters (graph-replay determinism).
__global__ void zero_state_kernel() {
    int i = blockIdx.x * blockDim.x + threadIdx.x;   // 262144 threads
    g_HC[i] = 0.f;
    g_Bh[i] = __float2half(0.f);
    if (i < 256) g_ctrs[i] = 0u;
}

// ---------------- A -> fp16 (x4096) ldmatrix tiles (once) ---------------------
__global__ void aconv_kernel(const float* __restrict__ A) {
    int idx = blockIdx.x * blockDim.x + threadIdx.x;
    int r = idx >> 9;
    int k = (idx & 511) << 3;
    int mt = r >> 7, rin = r & 127;
    int ktg = k >> 7, kin = k & 127;
    uint32_t byte = (uint32_t)(rin * 256 + ((((kin >> 3)) ^ (rin & 7)) << 4));
    size_t tile = ((size_t)(mt * 32 + ktg)) << 15;
    unsigned short h[8];
    #pragma unroll
    for (int i = 0; i < 8; i++) {
        float x = A[(size_t)r * NN + k + i] * A_SCALE;
        h[i] = __half_as_ushort(__float2half(x));
    }
    uint4 vh = make_uint4((uint32_t)h[0] | ((uint32_t)h[1] << 16),
                          (uint32_t)h[2] | ((uint32_t)h[3] << 16),
                          (uint32_t)h[4] | ((uint32_t)h[5] << 16),
                          (uint32_t)h[6] | ((uint32_t)h[7] << 16));
    *reinterpret_cast<uint4*>(reinterpret_cast<char*>(g_Ah) + tile + byte) = vh;
}

// ---------------- X -> Xr^T fp16 ldmatrix tiles (once) ------------------------
__global__ void xrconv_kernel(const float* __restrict__ X) {
    int idx = blockIdx.x * blockDim.x + threadIdx.x;
    int q  = idx >> 9;
    int kk = (idx & 511) << 3;
    int nt = q >> 6, rown = q & 63;
    int ktg = kk >> 7, kin = kk & 127;
    uint32_t byte = (uint32_t)(rown * 256 + ((((kin >> 3)) ^ (rown & 7)) << 4));
    size_t tile = ((size_t)(nt * 32 + ktg)) << 14;
    const bool valid = (q < TROLL * FIN);
    const int t = q / FIN, f = q - t * FIN;
    unsigned short h[8];
    #pragma unroll
    for (int i = 0; i < 8; i++) {
        float x = valid ? X[((size_t)t * NN + kk + i) * FIN + f] : 0.f;
        h[i] = __half_as_ushort(__float2half(x));
    }
    uint4 vh = make_uint4((uint32_t)h[0] | ((uint32_t)h[1] << 16),
                          (uint32_t)h[2] | ((uint32_t)h[3] << 16),
                          (uint32_t)h[4] | ((uint32_t)h[5] << 16),
                          (uint32_t)h[6] | ((uint32_t)h[7] << 16));
    *reinterpret_cast<uint4*>(reinterpret_cast<char*>(g_XBh) + tile + byte) = vh;
}

// ---------------- SMEM layout --------------------------------------------------
#define STG    49152          // stage: A 32K | B 16K
#define SM_B   32768
#define U_OFF  (3 * STG)                 // 147456: persistent U4 (52224 B)
#define SV_OFF (U_OFF + 52224)           // 199680: sv scratch (3328 B)
#define FS_SMEM (SV_OFF + 3328)          // 203008 total
#define C1_SMEM (2 * STG)

// ---------------- C1 = A @ Xr via single fp16 mma (one-time) -------------------
__global__ void __launch_bounds__(256, 1) c1_mma() {
    extern __shared__ __align__(16) char smem[];
    const int tid  = threadIdx.x;
    const int lane = tid & 31;
    const int wid  = tid >> 5;
    const int wm   = wid & 3;
    const int wn   = wid >> 2;
    const int mt   = blockIdx.x;
    const int nt   = blockIdx.y;
    const uint32_t sbase = smem_u32(smem);

    auto load_tile = [&](int kt, int b) {
        const char* gA = reinterpret_cast<const char*>(g_Ah) + (((size_t)(mt * 32 + kt)) << 15);
        const char* gB = reinterpret_cast<const char*>(g_XBh) + (((size_t)(nt * 32 + kt)) << 14);
        const uint32_t s = sbase + b * STG;
        #pragma unroll
        for (int i = 0; i < 8; i++)
            cp_async16(s + (tid + i * 256) * 16, gA + (tid + i * 256) * 16);
        #pragma unroll
        for (int i = 0; i < 4; i++)
            cp_async16(s + SM_B + (tid + i * 256) * 16, gB + (tid + i * 256) * 16);
        CP_COMMIT();
    };

    float acc[2][4][4];
    #pragma unroll
    for (int im = 0; im < 2; im++)
        #pragma unroll
        for (int jn = 0; jn < 4; jn++)
            #pragma unroll
            for (int q = 0; q < 4; q++) acc[im][jn][q] = 0.f;

    load_tile(0, 0);
    load_tile(1, 1);

    const int arow[2] = { wm * 32 + (lane & 15), wm * 32 + 16 + (lane & 15) };
    const int acolh   = (lane >> 4);
    const int nrow[2] = { wn * 32 + (lane & 7) + ((lane >> 4) << 3),
                          wn * 32 + 16 + (lane & 7) + ((lane >> 4) << 3) };
    const int bcolh   = (lane >> 3) & 1;

    for (int kt = 0; kt < 32; kt++) {
        const int b = kt & 1;
        if (kt == 31) asm volatile("cp.async.wait_group 0;" ::: "memory");
        else          asm volatile("cp.async.wait_group 1;" ::: "memory");
        __syncthreads();

        const uint32_t sA = sbase + b * STG;
        const uint32_t sB = sA + SM_B;

        #pragma unroll
        for (int ks = 0; ks < 8; ks++) {
            const int ck = ks * 2;
            uint32_t ah[2][4], bh[2][4];
            #pragma unroll
            for (int im = 0; im < 2; im++) {
                const int r = arow[im];
                ldm_x4(ah[im], sA + (uint32_t)(r * 256 + (((ck + acolh) ^ (r & 7)) << 4)));
            }
            #pragma unroll
            for (int g = 0; g < 2; g++) {
                const int r = nrow[g];
                ldm_x4(bh[g], sB + (uint32_t)(r * 256 + (((ck + bcolh) ^ (r & 7)) << 4)));
            }
            #pragma unroll
            for (int im = 0; im < 2; im++)
                #pragma unroll
                for (int jn = 0; jn < 4; jn++) {
                    const int g = jn >> 1, w = (jn & 1) * 2;
                    mma_f16(acc[im][jn], ah[im], bh[g][w], bh[g][w + 1]);
                }
        }
        __syncthreads();
        if (kt + 2 < 32) load_tile(kt + 2, b);
    }

    const int row0 = mt * 128 + wm * 32 + (lane >> 2);
    const int col0 = nt * 64 + wn * 32 + (lane & 3) * 2;
    #pragma unroll
    for (int im = 0; im < 2; im++)
        #pragma unroll
        for (int jn = 0; jn < 4; jn++) {
            const int r = row0 + im * 16;
            const int c = col0 + jn * 8;
            *reinterpret_cast<float2*>(&g_C1[(size_t)r * 1024 + c]) =
                make_float2(acc[im][jn][0] * A_INV, acc[im][jn][1] * A_INV);
            *reinterpret_cast<float2*>(&g_C1[(size_t)(r + 8) * 1024 + c]) =
                make_float2(acc[im][jn][2] * A_INV, acc[im][jn][3] * A_INV);
        }
}

// ---------------- spread-counter grid barrier ----------------------------------
// 8 counters, 16 CTAs each (parallel arrivals); 8 threads poll in parallel.
__device__ __forceinline__ void grid_sync(unsigned q) {
    __syncthreads();
    if (threadIdx.x == 0) {
        __threadfence();
        atomicAdd(&g_ctrs[(blockIdx.x & 7) * 32], 1u);
    }
    if (threadIdx.x < 8) {
        const unsigned goal = q * 16u;
        unsigned v;
        do {
            asm volatile("ld.acquire.gpu.global.u32 %0, [%1];"
                         : "=r"(v) : "l"(&g_ctrs[threadIdx.x * 32]) : "memory");
        } while (v < goal);
    }
    __syncthreads();
}

// ---------------- persistent fused step loop -----------------------------------
// 3-stage pipeline (kt mod 3), persistent U table in smem, cross-barrier A prefetch.
__global__ void __launch_bounds__(256, 1) fused_steps(const float* __restrict__ W_fc,
                                                      const float* __restrict__ b_fc,
                                                      float* __restrict__ out) {
    extern __shared__ __align__(16) char smem[];
    const int tid  = threadIdx.x;
    const int lane = tid & 31;
    const int wid  = tid >> 5;
    const int wm   = wid & 3;
    const int wn   = wid >> 2;
    const int bid  = blockIdx.x;
    const int mt   = bid >> 2;
    const int z    = bid & 3;
    const uint32_t sbase = smem_u32(smem);

    // persistent U table (loaded once)
    float4* Us4 = reinterpret_cast<float4*>(smem + U_OFF);
    {
        const float4* gU4 = reinterpret_cast<const float4*>(g_U4);
        for (int i = tid; i < 3264; i += 256) Us4[i] = gU4[i];
    }
    float* svall = reinterpret_cast<float*>(smem + SV_OFF);
    __syncthreads();

    auto issueA = [&](int kt) {               // A half of tile kt -> stage kt%3
        const char* gA = reinterpret_cast<const char*>(g_Ah)
                       + (((size_t)(mt * 32 + z * 8 + kt)) << 15);
        const uint32_t d = sbase + (kt % 3) * STG;
        #pragma unroll
        for (int i = 0; i < 8; i++)
            cp_async16(d + (tid + i * 256) * 16, gA + (tid + i * 256) * 16);
    };
    auto issueB = [&](int kt) {               // B half of tile kt -> stage kt%3 + SM_B
        const char* gB = reinterpret_cast<const char*>(g_Bh)
                       + ((size_t)(z * 8 + kt) << 14);
        const uint32_t d = sbase + (kt % 3) * STG + SM_B;
        #pragma unroll
        for (int i = 0; i < 4; i++)
            cp_async16(d + (tid + i * 256) * 16, gB + (tid + i * 256) * 16);
    };

    const int arow[2] = { wm * 32 + (lane & 15), wm * 32 + 16 + (lane & 15) };
    const int acolh   = (lane >> 4);
    const int nrow[2] = { wn * 32 + (lane & 7) + ((lane >> 4) << 3),
                          wn * 32 + 16 + (lane & 7) + ((lane >> 4) << 3) };
    const int bcolh   = (lane >> 3) & 1;

    // prefetch A for step 0 tiles 0,1 (two groups)
    issueA(0); CP_COMMIT();
    issueA(1); CP_COMMIT();

    unsigned q = 0;

    for (int t = 0; t < TROLL; t++) {
        // B halves for tiles 0,1 (one group); full tile 2 (one group)
        issueB(0); issueB(1); CP_COMMIT();
        issueA(2); issueB(2); CP_COMMIT();

        float acc[2][4][4];
        #pragma unroll
        for (int im = 0; im < 2; im++)
            #pragma unroll
            for (int jn = 0; jn < 4; jn++)
                #pragma unroll
                for (int p = 0; p < 4; p++) acc[im][jn][p] = 0.f;

        #pragma unroll
        for (int kt = 0; kt < NKT; kt++) {
            // hand-scheduled waits: 2 groups of lookahead in steady state
            if (kt == 0 || kt >= 6) asm volatile("cp.async.wait_group 1;" ::: "memory");
            else                    asm volatile("cp.async.wait_group 2;" ::: "memory");
            __syncthreads();

            const uint32_t sA = sbase + (kt % 3) * STG;
            const uint32_t sB = sA + SM_B;

            #pragma unroll
            for (int ks = 0; ks < 8; ks++) {
                const int ck = ks * 2;
                uint32_t ah[2][4], bh[2][4];
                #pragma unroll
                for (int im = 0; im < 2; im++) {
                    const int r = arow[im];
                    ldm_x4(ah[im], sA + (uint32_t)(r * 256 + (((ck + acolh) ^ (r & 7)) << 4)));
                }
                #pragma unroll
                for (int g = 0; g < 2; g++) {
                    const int r = nrow[g];
                    ldm_x4(bh[g], sB + (uint32_t)(r * 256 + (((ck + bcolh) ^ (r & 7)) << 4)));
                }
                #pragma unroll
                for (int im = 0; im < 2; im++)
                    #pragma unroll
                    for (int jn = 0; jn < 4; jn++) {
                        const int g = jn >> 1, w = (jn & 1) * 2;
                        mma_f16(acc[im][jn], ah[im], bh[g][w], bh[g][w + 1]);
                    }
            }
            __syncthreads();

            if (kt + 3 < NKT) { issueA(kt + 3); issueB(kt + 3); CP_COMMIT(); }
            else if (kt == 6) { issueA(0); CP_COMMIT(); }   // next-step A prefetch
            else if (kt == 7) { issueA(1); CP_COMMIT(); }
        }

        {
            float* base = g_Mpart + (size_t)z * NN * 64;
            const int row0 = mt * 128 + wm * 32 + (lane >> 2);
            const int col0 = wn * 32 + (lane & 3) * 2;
            #pragma unroll
            for (int im = 0; im < 2; im++)
                #pragma unroll
                for (int jn = 0; jn < 4; jn++) {
                    const int r = row0 + im * 16;
                    const int c = col0 + jn * 8;
                    *reinterpret_cast<float2*>(&base[(size_t)r * 64 + c]) =
                        make_float2(acc[im][jn][0] * AB_INV, acc[im][jn][1] * AB_INV);
                    *reinterpret_cast<float2*>(&base[(size_t)(r + 8) * 64 + c]) =
                        make_float2(acc[im][jn][2] * AB_INV, acc[im][jn][3] * AB_INV);
                }
        }

        grid_sync(++q);

        // ================= phase B: gates (persistent U) =================
        {
            float* sv = svall + wid * 104;
            const float4 bb = Us4[3232 + lane];

            #pragma unroll
            for (int it = 0; it < 4; it++) {
                const int n = bid * 32 + wid * 4 + it;
                float m0 = 0.f, m1 = 0.f;
                #pragma unroll
                for (int zz = 0; zz < MSPLIT; zz++) {
                    m0 += g_Mpart[((size_t)zz * NN + n) * 64 + lane];
                    m1 += g_Mpart[((size_t)zz * NN + n) * 64 + 32 + lane];
                }
                const float h_old = g_HC[n * 64 + lane];
                const float c_old = g_HC[n * 64 + 32 + lane];
                sv[lane]      = m0;
                sv[32 + lane] = m1;
                sv[64 + lane] = h_old;
                if (lane < FIN) sv[96 + lane] = g_C1[(size_t)n * 1024 + t * FIN + lane];
                __syncwarp();

                u64 a01 = pack2(bb.x, bb.y);
                u64 a23 = pack2(bb.z, bb.w);
                #pragma unroll
                for (int k = 0; k < 101; k++) {
                    const float s = sv[k];
                    const u64 ss = pack2(s, s);
                    const float4 u4 = Us4[k * 32 + lane];
                    ffma2(a01, pack2(u4.x, u4.y), ss);
                    ffma2(a23, pack2(u4.z, u4.w), ss);
                }
                float gi, gf, gg, go;
                unpack2(a01, gi, gf);
                unpack2(a23, gg, go);

                const float ii = 1.f / (1.f + expf(-gi));
                const float ff = 1.f / (1.f + expf(-gf));
                const float g3 = tanhf(gg);
                const float oo = 1.f / (1.f + expf(-go));
                const float c_new = ff * c_old + ii * g3;
                const float h_new = oo * tanhf(c_new);
                g_HC[n * 64 + lane]      = h_new;
                g_HC[n * 64 + 32 + lane] = c_new;

                // B-tile writes (fp16, x256; tile ktg = n>>7 at ktg<<14)
                const int ktg = n >> 7, kin = n & 127;
                const size_t tbase = (size_t)ktg << 14;
                const uint32_t kpart = (uint32_t)(((kin >> 3) & 0xF) << 4);
                const uint32_t klow  = (uint32_t)((kin & 7) * 2);
                char* const pB = reinterpret_cast<char*>(g_Bh) + tbase;

                const __half hh = __float2half(h_new * B_SCALE);
                const __half ch = __float2half(c_new * B_SCALE);

                const uint32_t bh_row = (uint32_t)lane;
                const uint32_t bc_row = (uint32_t)(lane + 32);
                const uint32_t offh = bh_row * 256 + (kpart ^ ((bh_row & 7) << 4)) + klow;
                const uint32_t offc = bc_row * 256 + (kpart ^ ((bc_row & 7) << 4)) + klow;
                *reinterpret_cast<__half*>(pB + offh) = hh;
                *reinterpret_cast<__half*>(pB + offc) = ch;
                __syncwarp();
            }
        }

        grid_sync(++q);
    }

    asm volatile("cp.async.wait_group 0;" ::: "memory");

    // ---- final projection for own nodes ----
    if (tid < 32) {
        const int n = bid * 32 + tid;
        float s = b_fc[0];
        #pragma unroll
        for (int u = 0; u < HDIM; u++) s += g_HC[n * 64 + u] * W_fc[u];
        out[n] = s;
    }
}

// ---------------- launch --------------------------------------------------------
extern "C" void kernel_launch(void* const* d_in, const int* in_sizes, int n_in,
                              void* d_out, int out_size) {
    const float* X    = (const float*)d_in[0];
    const float* A    = (const float*)d_in[1];
    const float* Wx   = (const float*)d_in[2];
    const float* Wh   = (const float*)d_in[3];
    const float* Wc   = (const float*)d_in[4];
    const float* W_ih = (const float*)d_in[5];
    const float* W_hh = (const float*)d_in[6];
    const float* b_ih = (const float*)d_in[7];
    const float* b_hh = (const float*)d_in[8];
    const float* W_fc = (const float*)d_in[9];
    const float* b_fc = (const float*)d_in[10];

    cudaFuncSetAttribute(c1_mma, cudaFuncAttributeMaxDynamicSharedMemorySize, C1_SMEM);
    cudaFuncSetAttribute(fused_steps, cudaFuncAttributeMaxDynamicSharedMemorySize, FS_SMEM);

    setup_kernel<<<1, 128>>>(Wx, Wh, Wc, W_ih, W_hh, b_ih, b_hh);
    zero_state_kernel<<<(NN * 64) / 256, 256>>>();
    xrconv_kernel<<<(1024 * 512) / 256, 256>>>(X);
    aconv_kernel<<<(NN * 512) / 256, 256>>>(A);
    c1_mma<<<dim3(32, 16), 256, C1_SMEM>>>();
    fused_steps<<<NCTA, 256, FS_SMEM>>>(W_fc, b_fc, (float*)d_out);
}

// round 17
// speedup vs baseline: 1.2323x; 1.0332x over previous
#include <cuda_runtime.h>
#include <cuda_fp16.h>
#include <math.h>
#include <cstdint>

// Problem constants
#define NN    4096
#define HDIM  32
#define TROLL 200
#define FIN   5

#define MSPLIT 4               // K-split for step GEMM; each CTA does K=1024
#define NKT    8               // k-tiles per step CTA
#define NCTA   128             // persistent grid size (mt*4 + z)

// fp16 scaling: A stored x4096 (avoids subnormals); B (h,c) stored x256.
#define A_SCALE   4096.0f
#define B_SCALE   256.0f
#define AB_INV    (1.0f / (4096.0f * 256.0f))
#define A_INV     (1.0f / 4096.0f)

typedef unsigned long long u64;

// ---------------- fp32x2 / mma helpers ---------------------------------------
__device__ __forceinline__ u64 pack2(float x, float y) {
    u64 r; asm("mov.b64 %0, {%1, %2};" : "=l"(r) : "f"(x), "f"(y)); return r;
}
__device__ __forceinline__ void unpack2(u64 v, float& x, float& y) {
    asm("mov.b64 {%0, %1}, %2;" : "=f"(x), "=f"(y) : "l"(v));
}
__device__ __forceinline__ void ffma2(u64& d, u64 a, u64 b) {
    asm("fma.rn.f32x2 %0, %1, %2, %0;" : "+l"(d) : "l"(a), "l"(b));
}
__device__ __forceinline__ uint32_t smem_u32(const void* p) {
    uint32_t a;
    asm("{ .reg .u64 t; cvta.to.shared.u64 t, %1; cvt.u32.u64 %0, t; }" : "=r"(a) : "l"(p));
    return a;
}
__device__ __forceinline__ void ldm_x4(uint32_t* r, uint32_t addr) {
    asm volatile("ldmatrix.sync.aligned.m8n8.x4.shared.b16 {%0,%1,%2,%3}, [%4];"
        : "=r"(r[0]), "=r"(r[1]), "=r"(r[2]), "=r"(r[3]) : "r"(addr));
}
__device__ __forceinline__ void mma_f16(float* d, const uint32_t* a, uint32_t b0, uint32_t b1) {
    asm volatile("mma.sync.aligned.m16n8k16.row.col.f32.f16.f16.f32 "
        "{%0,%1,%2,%3}, {%4,%5,%6,%7}, {%8,%9}, {%0,%1,%2,%3};"
        : "+f"(d[0]), "+f"(d[1]), "+f"(d[2]), "+f"(d[3])
        : "r"(a[0]), "r"(a[1]), "r"(a[2]), "r"(a[3]), "r"(b0), "r"(b1));
}
__device__ __forceinline__ void cp_async16(uint32_t saddr, const void* gaddr) {
    asm volatile("cp.async.cg.shared.global [%0], [%1], 16;"
        :: "r"(saddr), "l"(gaddr) : "memory");
}
#define CP_COMMIT() asm volatile("cp.async.commit_group;" ::: "memory")

// ---------------- device scratch ---------------------------------------------
__device__ __align__(16) float g_HC[NN * 64];                      // [n][0:32]=h,[32:64]=c
__device__ __align__(16) float g_Mpart[(size_t)MSPLIT * NN * 64];  // K-split partials
__device__ __align__(16) float g_C1[(size_t)NN * 1024];            // A @ Xr (fp32)
__device__ __align__(16) float g_U[101 * 128];
__device__ __align__(16) float g_bias[128];
__device__ __align__(16) float g_U4[13056];                        // [(k*32+l)*4+q]=U[k][l+32q]; +bias4
__device__ __align__(128) unsigned g_ctrs[256];                    // global barrier counters ([i*32], i<8)
__device__ __align__(128) unsigned g_gctrs[1024];                  // per-mt group counters ([mt*32])
// A (x4096) fp16, ldmatrix-ready 128x128 tiles.
// tile (mt, ktg) at ((mt*32+ktg) << 15); byte(row,k)=row*256+(((k>>3)^(row&7))<<4)+(k&7)*2
__device__ __align__(16) __half g_Ah[(size_t)NN * NN];
// HC^T (x256) fp16, 64x128 tiles (16KB), tile ktg at (ktg<<14)
__device__ __align__(16) __half g_Bh[(size_t)64 * NN];
// Xr^T fp16, 64x128 tiles, tile (ktg,nt) at ((nt*32+ktg)<<14)
__device__ __align__(16) __half g_XBh[(size_t)1024 * NN];

// ---------------- setup: fused gate matrix U + repacked U4 -------------------
__global__ void setup_kernel(const float* __restrict__ Wx, const float* __restrict__ Wh,
                             const float* __restrict__ Wc, const float* __restrict__ W_ih,
                             const float* __restrict__ W_hh, const float* __restrict__ b_ih,
                             const float* __restrict__ b_hh) {
    const int j = threadIdx.x;
    __shared__ float sWih[128 * 32];
    for (int i = j; i < 128 * 32; i += 128) sWih[i] = W_ih[i];
    __syncthreads();
    for (int r = 0; r < 32; r++) {
        float s = 0.f;
        for (int m = 0; m < 32; m++) s += Wh[r * 32 + m] * sWih[j * 32 + m];
        g_U[r * 128 + j] = s;
    }
    for (int r = 0; r < 32; r++) {
        float s = 0.f;
        for (int m = 0; m < 32; m++) s += Wc[r * 32 + m] * sWih[j * 32 + m];
        g_U[(32 + r) * 128 + j] = s;
    }
    for (int m = 0; m < 32; m++) g_U[(64 + m) * 128 + j] = W_hh[j * 32 + m];
    for (int f = 0; f < FIN; f++) {
        float s = 0.f;
        for (int m = 0; m < 32; m++) s += Wx[f * 32 + m] * sWih[j * 32 + m];
        g_U[(96 + f) * 128 + j] = s;
    }
    g_bias[j] = b_ih[j] + b_hh[j];
    __syncthreads();
    {
        const int l = j & 31, q = j >> 5;
        for (int k = 0; k < 101; k++)
            g_U4[(k * 32 + l) * 4 + q] = g_U[k * 128 + l + 32 * q];
        g_U4[(101 * 32 + l) * 4 + q] = g_bias[l + 32 * q];
    }
}

// Zero h/c, B tiles, and barrier counters (graph-replay determinism).
__global__ void zero_state_kernel() {
    int i = blockIdx.x * blockDim.x + threadIdx.x;   // 262144 threads
    g_HC[i] = 0.f;
    g_Bh[i] = __float2half(0.f);
    if (i < 256) g_ctrs[i] = 0u;
    if (i < 1024) g_gctrs[i] = 0u;
}

// ---------------- A -> fp16 (x4096) ldmatrix tiles (once) ---------------------
__global__ void aconv_kernel(const float* __restrict__ A) {
    int idx = blockIdx.x * blockDim.x + threadIdx.x;
    int r = idx >> 9;
    int k = (idx & 511) << 3;
    int mt = r >> 7, rin = r & 127;
    int ktg = k >> 7, kin = k & 127;
    uint32_t byte = (uint32_t)(rin * 256 + ((((kin >> 3)) ^ (rin & 7)) << 4));
    size_t tile = ((size_t)(mt * 32 + ktg)) << 15;
    unsigned short h[8];
    #pragma unroll
    for (int i = 0; i < 8; i++) {
        float x = A[(size_t)r * NN + k + i] * A_SCALE;
        h[i] = __half_as_ushort(__float2half(x));
    }
    uint4 vh = make_uint4((uint32_t)h[0] | ((uint32_t)h[1] << 16),
                          (uint32_t)h[2] | ((uint32_t)h[3] << 16),
                          (uint32_t)h[4] | ((uint32_t)h[5] << 16),
                          (uint32_t)h[6] | ((uint32_t)h[7] << 16));
    *reinterpret_cast<uint4*>(reinterpret_cast<char*>(g_Ah) + tile + byte) = vh;
}

// ---------------- X -> Xr^T fp16 ldmatrix tiles (once) ------------------------
__global__ void xrconv_kernel(const float* __restrict__ X) {
    int idx = blockIdx.x * blockDim.x + threadIdx.x;
    int q  = idx >> 9;
    int kk = (idx & 511) << 3;
    int nt = q >> 6, rown = q & 63;
    int ktg = kk >> 7, kin = kk & 127;
    uint32_t byte = (uint32_t)(rown * 256 + ((((kin >> 3)) ^ (rown & 7)) << 4));
    size_t tile = ((size_t)(nt * 32 + ktg)) << 14;
    const bool valid = (q < TROLL * FIN);
    const int t = q / FIN, f = q - t * FIN;
    unsigned short h[8];
    #pragma unroll
    for (int i = 0; i < 8; i++) {
        float x = valid ? X[((size_t)t * NN + kk + i) * FIN + f] : 0.f;
        h[i] = __half_as_ushort(__float2half(x));
    }
    uint4 vh = make_uint4((uint32_t)h[0] | ((uint32_t)h[1] << 16),
                          (uint32_t)h[2] | ((uint32_t)h[3] << 16),
                          (uint32_t)h[4] | ((uint32_t)h[5] << 16),
                          (uint32_t)h[6] | ((uint32_t)h[7] << 16));
    *reinterpret_cast<uint4*>(reinterpret_cast<char*>(g_XBh) + tile + byte) = vh;
}

// ---------------- SMEM layout --------------------------------------------------
#define STG    49152          // stage: A 32K | B 16K
#define SM_B   32768
#define U_OFF  (3 * STG)                 // 147456: persistent U4 (52224 B)
#define SV_OFF (U_OFF + 52224)           // 199680: sv scratch (3328 B)
#define FS_SMEM (SV_OFF + 3328)          // 203008 total
#define C1_SMEM (2 * STG)

// ---------------- C1 = A @ Xr via single fp16 mma (one-time) -------------------
__global__ void __launch_bounds__(256, 1) c1_mma() {
    extern __shared__ __align__(16) char smem[];
    const int tid  = threadIdx.x;
    const int lane = tid & 31;
    const int wid  = tid >> 5;
    const int wm   = wid & 3;
    const int wn   = wid >> 2;
    const int mt   = blockIdx.x;
    const int nt   = blockIdx.y;
    const uint32_t sbase = smem_u32(smem);

    auto load_tile = [&](int kt, int b) {
        const char* gA = reinterpret_cast<const char*>(g_Ah) + (((size_t)(mt * 32 + kt)) << 15);
        const char* gB = reinterpret_cast<const char*>(g_XBh) + (((size_t)(nt * 32 + kt)) << 14);
        const uint32_t s = sbase + b * STG;
        #pragma unroll
        for (int i = 0; i < 8; i++)
            cp_async16(s + (tid + i * 256) * 16, gA + (tid + i * 256) * 16);
        #pragma unroll
        for (int i = 0; i < 4; i++)
            cp_async16(s + SM_B + (tid + i * 256) * 16, gB + (tid + i * 256) * 16);
        CP_COMMIT();
    };

    float acc[2][4][4];
    #pragma unroll
    for (int im = 0; im < 2; im++)
        #pragma unroll
        for (int jn = 0; jn < 4; jn++)
            #pragma unroll
            for (int q = 0; q < 4; q++) acc[im][jn][q] = 0.f;

    load_tile(0, 0);
    load_tile(1, 1);

    const int arow[2] = { wm * 32 + (lane & 15), wm * 32 + 16 + (lane & 15) };
    const int acolh   = (lane >> 4);
    const int nrow[2] = { wn * 32 + (lane & 7) + ((lane >> 4) << 3),
                          wn * 32 + 16 + (lane & 7) + ((lane >> 4) << 3) };
    const int bcolh   = (lane >> 3) & 1;

    for (int kt = 0; kt < 32; kt++) {
        const int b = kt & 1;
        if (kt == 31) asm volatile("cp.async.wait_group 0;" ::: "memory");
        else          asm volatile("cp.async.wait_group 1;" ::: "memory");
        __syncthreads();

        const uint32_t sA = sbase + b * STG;
        const uint32_t sB = sA + SM_B;

        #pragma unroll
        for (int ks = 0; ks < 8; ks++) {
            const int ck = ks * 2;
            uint32_t ah[2][4], bh[2][4];
            #pragma unroll
            for (int im = 0; im < 2; im++) {
                const int r = arow[im];
                ldm_x4(ah[im], sA + (uint32_t)(r * 256 + (((ck + acolh) ^ (r & 7)) << 4)));
            }
            #pragma unroll
            for (int g = 0; g < 2; g++) {
                const int r = nrow[g];
                ldm_x4(bh[g], sB + (uint32_t)(r * 256 + (((ck + bcolh) ^ (r & 7)) << 4)));
            }
            #pragma unroll
            for (int im = 0; im < 2; im++)
                #pragma unroll
                for (int jn = 0; jn < 4; jn++) {
                    const int g = jn >> 1, w = (jn & 1) * 2;
                    mma_f16(acc[im][jn], ah[im], bh[g][w], bh[g][w + 1]);
                }
        }
        __syncthreads();
        if (kt + 2 < 32) load_tile(kt + 2, b);
    }

    const int row0 = mt * 128 + wm * 32 + (lane >> 2);
    const int col0 = nt * 64 + wn * 32 + (lane & 3) * 2;
    #pragma unroll
    for (int im = 0; im < 2; im++)
        #pragma unroll
        for (int jn = 0; jn < 4; jn++) {
            const int r = row0 + im * 16;
            const int c = col0 + jn * 8;
            *reinterpret_cast<float2*>(&g_C1[(size_t)r * 1024 + c]) =
                make_float2(acc[im][jn][0] * A_INV, acc[im][jn][1] * A_INV);
            *reinterpret_cast<float2*>(&g_C1[(size_t)(r + 8) * 1024 + c]) =
                make_float2(acc[im][jn][2] * A_INV, acc[im][jn][3] * A_INV);
        }
}

// ---------------- barriers ------------------------------------------------------
// global: 8 spread counters, 16 CTAs each
__device__ __forceinline__ void grid_sync(unsigned q) {
    __syncthreads();
    if (threadIdx.x == 0) {
        __threadfence();
        atomicAdd(&g_ctrs[(blockIdx.x & 7) * 32], 1u);
    }
    if (threadIdx.x < 8) {
        const unsigned goal = q * 16u;
        unsigned v;
        do {
            asm volatile("ld.acquire.gpu.global.u32 %0, [%1];"
                         : "=r"(v) : "l"(&g_ctrs[threadIdx.x * 32]) : "memory");
        } while (v < goal);
    }
    __syncthreads();
}
// group: 4 CTAs sharing M-tile mt
__device__ __forceinline__ void group_sync(int mt, unsigned goal) {
    __syncthreads();
    if (threadIdx.x == 0) {
        __threadfence();
        atomicAdd(&g_gctrs[mt * 32], 1u);
        unsigned v;
        do {
            asm volatile("ld.acquire.gpu.global.u32 %0, [%1];"
                         : "=r"(v) : "l"(&g_gctrs[mt * 32]) : "memory");
        } while (v < goal);
    }
    __syncthreads();
}

// ---------------- persistent fused step loop -----------------------------------
// Per step: mma -> Mpart; 4-CTA group sync; gates (Mpart+HC staged into the idle
// stage-2 SMEM via cp.async, waited with wait_group 0) -> HC + B tiles; ONE
// global barrier. Next-step A prefetch issued AFTER the staging wait so the
// cp.async group FIFO is exact (R16 bug: prefetch groups ahead of staging
// groups made wait_group 2 retire the wrong ones).
__global__ void __launch_bounds__(256, 1) fused_steps(const float* __restrict__ W_fc,
                                                      const float* __restrict__ b_fc,
                                                      float* __restrict__ out) {
    extern __shared__ __align__(16) char smem[];
    const int tid  = threadIdx.x;
    const int lane = tid & 31;
    const int wid  = tid >> 5;
    const int wm   = wid & 3;
    const int wn   = wid >> 2;
    const int bid  = blockIdx.x;
    const int mt   = bid >> 2;
    const int z    = bid & 3;
    const uint32_t sbase = smem_u32(smem);

    // persistent U table (loaded once)
    float4* Us4 = reinterpret_cast<float4*>(smem + U_OFF);
    {
        const float4* gU4 = reinterpret_cast<const float4*>(g_U4);
        for (int i = tid; i < 3264; i += 256) Us4[i] = gU4[i];
    }
    float* svall = reinterpret_cast<float*>(smem + SV_OFF);
    __syncthreads();

    auto issueA = [&](int kt) {               // A half of tile kt -> stage kt%3
        const char* gA = reinterpret_cast<const char*>(g_Ah)
                       + (((size_t)(mt * 32 + z * 8 + kt)) << 15);
        const uint32_t d = sbase + (kt % 3) * STG;
        #pragma unroll
        for (int i = 0; i < 8; i++)
            cp_async16(d + (tid + i * 256) * 16, gA + (tid + i * 256) * 16);
    };
    auto issueB = [&](int kt) {               // B half of tile kt -> stage kt%3 + SM_B
        const char* gB = reinterpret_cast<const char*>(g_Bh)
                       + ((size_t)(z * 8 + kt) << 14);
        const uint32_t d = sbase + (kt % 3) * STG + SM_B;
        #pragma unroll
        for (int i = 0; i < 4; i++)
            cp_async16(d + (tid + i * 256) * 16, gB + (tid + i * 256) * 16);
    };

    const int arow[2] = { wm * 32 + (lane & 15), wm * 32 + 16 + (lane & 15) };
    const int acolh   = (lane >> 4);
    const int nrow[2] = { wn * 32 + (lane & 7) + ((lane >> 4) << 3),
                          wn * 32 + 16 + (lane & 7) + ((lane >> 4) << 3) };
    const int bcolh   = (lane >> 3) & 1;

    // prefetch A for step 0 tiles 0,1 (two groups)
    issueA(0); CP_COMMIT();
    issueA(1); CP_COMMIT();

    unsigned q = 0;

    for (int t = 0; t < TROLL; t++) {
        // FIFO entering mainloop: [A0, A1, B01, A2B2]
        issueB(0); issueB(1); CP_COMMIT();
        issueA(2); issueB(2); CP_COMMIT();

        float acc[2][4][4];
        #pragma unroll
        for (int im = 0; im < 2; im++)
            #pragma unroll
            for (int jn = 0; jn < 4; jn++)
                #pragma unroll
                for (int p = 0; p < 4; p++) acc[im][jn][p] = 0.f;

        #pragma unroll
        for (int kt = 0; kt < NKT; kt++) {
            // exact FIFO accounting (no prefetch in tail this time):
            // kt=0: [A0,A1,B01,A2B2] need B01      -> wait 1
            // kt=1..5: steady, 3 tile-groups ahead -> wait 2
            // kt=6: [T6,T7] need T6                -> wait 1
            // kt=7: [T7]    need T7                -> wait 0
            if (kt == 0 || kt == 6)      asm volatile("cp.async.wait_group 1;" ::: "memory");
            else if (kt == 7)            asm volatile("cp.async.wait_group 0;" ::: "memory");
            else                         asm volatile("cp.async.wait_group 2;" ::: "memory");
            __syncthreads();

            const uint32_t sA = sbase + (kt % 3) * STG;
            const uint32_t sB = sA + SM_B;

            #pragma unroll
            for (int ks = 0; ks < 8; ks++) {
                const int ck = ks * 2;
                uint32_t ah[2][4], bh[2][4];
                #pragma unroll
                for (int im = 0; im < 2; im++) {
                    const int r = arow[im];
                    ldm_x4(ah[im], sA + (uint32_t)(r * 256 + (((ck + acolh) ^ (r & 7)) << 4)));
                }
                #pragma unroll
                for (int g = 0; g < 2; g++) {
                    const int r = nrow[g];
                    ldm_x4(bh[g], sB + (uint32_t)(r * 256 + (((ck + bcolh) ^ (r & 7)) << 4)));
                }
                #pragma unroll
                for (int im = 0; im < 2; im++)
                    #pragma unroll
                    for (int jn = 0; jn < 4; jn++) {
                        const int g = jn >> 1, w = (jn & 1) * 2;
                        mma_f16(acc[im][jn], ah[im], bh[g][w], bh[g][w + 1]);
                    }
            }
            __syncthreads();

            if (kt + 3 < NKT) { issueA(kt + 3); issueB(kt + 3); CP_COMMIT(); }
        }

        // ---- epilogue: Mpart writes ----
        {
            float* base = g_Mpart + (size_t)z * NN * 64;
            const int row0 = mt * 128 + wm * 32 + (lane >> 2);
            const int col0 = wn * 32 + (lane & 3) * 2;
            #pragma unroll
            for (int im = 0; im < 2; im++)
                #pragma unroll
                for (int jn = 0; jn < 4; jn++) {
                    const int r = row0 + im * 16;
                    const int c = col0 + jn * 8;
                    *reinterpret_cast<float2*>(&base[(size_t)r * 64 + c]) =
                        make_float2(acc[im][jn][0] * AB_INV, acc[im][jn][1] * AB_INV);
                    *reinterpret_cast<float2*>(&base[(size_t)(r + 8) * 64 + c]) =
                        make_float2(acc[im][jn][2] * AB_INV, acc[im][jn][3] * AB_INV);
                }
        }

        // ---- stage HC (own nodes) into stage-2 SMEM before group sync ----
        {
            const uint32_t std_ = sbase + 2 * STG + 32768;
            #pragma unroll
            for (int i = 0; i < 2; i++) {
                const int o = i * 256 + tid;      // 512 chunks: 32 nodes x 16 x 16B
                const int nloc = o >> 4;
                const int c16 = o & 15;
                const char* src = reinterpret_cast<const char*>(g_HC)
                                + (size_t)(bid * 32 + nloc) * 256 + c16 * 16;
                cp_async16(std_ + (uint32_t)(nloc * 256 + c16 * 16), src);
            }
            CP_COMMIT();                          // FIFO: [HC]
        }
        // C1 values for this step (plain loads, independent of Mpart)
        float c1v[4];
        if (lane < FIN) {
            #pragma unroll
            for (int it = 0; it < 4; it++)
                c1v[it] = g_C1[(size_t)(bid * 32 + wid * 4 + it) * 1024 + t * FIN + lane];
        }

        // ---- 4-CTA group sync: Mpart of group mt visible ----
        group_sync(mt, (unsigned)(t + 1) * 4u);

        // ---- stage Mpart (group's K-split partials for own 32 nodes) ----
        {
            const uint32_t std_ = sbase + 2 * STG;
            #pragma unroll
            for (int i = 0; i < 8; i++) {
                const int o = i * 256 + tid;      // 2048 chunks: 4z x 32 nodes x 16 x 16B
                const int zz = o >> 9;
                const int nloc = (o >> 4) & 31;
                const int c16 = o & 15;
                const char* src = reinterpret_cast<const char*>(g_Mpart)
                                + ((size_t)(zz * NN + bid * 32 + nloc)) * 256 + c16 * 16;
                cp_async16(std_ + (uint32_t)((nloc * 4 + zz) * 256 + c16 * 16), src);
            }
            CP_COMMIT();                          // FIFO: [HC, Mpart]
        }
        asm volatile("cp.async.wait_group 0;" ::: "memory");   // BOTH staged groups done
        __syncthreads();

        // next-step A prefetch AFTER staging wait (overlaps gates + barrier)
        issueA(0); CP_COMMIT();
        issueA(1); CP_COMMIT();                   // FIFO at next mainloop: [A0, A1]

        // ================= gates (all inputs in SMEM) =================
        {
            float* sMp  = reinterpret_cast<float*>(smem + 2 * STG);
            float* sHCs = reinterpret_cast<float*>(smem + 2 * STG + 32768);
            float* sv = svall + wid * 104;
            const float4 bb = Us4[3232 + lane];

            #pragma unroll
            for (int it = 0; it < 4; it++) {
                const int nloc = wid * 4 + it;
                const int n = bid * 32 + nloc;
                float m0 = 0.f, m1 = 0.f;
                #pragma unroll
                for (int zz = 0; zz < MSPLIT; zz++) {
                    m0 += sMp[(nloc * 4 + zz) * 64 + lane];
                    m1 += sMp[(nloc * 4 + zz) * 64 + 32 + lane];
                }
                const float h_old = sHCs[nloc * 64 + lane];
                const float c_old = sHCs[nloc * 64 + 32 + lane];
                sv[lane]      = m0;
                sv[32 + lane] = m1;
                sv[64 + lane] = h_old;
                if (lane < FIN) sv[96 + lane] = c1v[it];
                __syncwarp();

                u64 a01 = pack2(bb.x, bb.y);
                u64 a23 = pack2(bb.z, bb.w);
                #pragma unroll
                for (int k = 0; k < 101; k++) {
                    const float s = sv[k];
                    const u64 ss = pack2(s, s);
                    const float4 u4 = Us4[k * 32 + lane];
                    ffma2(a01, pack2(u4.x, u4.y), ss);
                    ffma2(a23, pack2(u4.z, u4.w), ss);
                }
                float gi, gf, gg, go;
                unpack2(a01, gi, gf);
                unpack2(a23, gg, go);

                const float ii = 1.f / (1.f + expf(-gi));
                const float ff = 1.f / (1.f + expf(-gf));
                const float g3 = tanhf(gg);
                const float oo = 1.f / (1.f + expf(-go));
                const float c_new = ff * c_old + ii * g3;
                const float h_new = oo * tanhf(c_new);
                g_HC[n * 64 + lane]      = h_new;
                g_HC[n * 64 + 32 + lane] = c_new;

                // B-tile writes (fp16, x256; tile ktg = n>>7 at ktg<<14)
                const int ktg = n >> 7, kin = n & 127;
                const size_t tbase = (size_t)ktg << 14;
                const uint32_t kpart = (uint32_t)(((kin >> 3) & 0xF) << 4);
                const uint32_t klow  = (uint32_t)((kin & 7) * 2);
                char* const pB = reinterpret_cast<char*>(g_Bh) + tbase;

                const __half hh = __float2half(h_new * B_SCALE);
                const __half ch = __float2half(c_new * B_SCALE);

                const uint32_t bh_row = (uint32_t)lane;
                const uint32_t bc_row = (uint32_t)(lane + 32);
                const uint32_t offh = bh_row * 256 + (kpart ^ ((bh_row & 7) << 4)) + klow;
                const uint32_t offc = bc_row * 256 + (kpart ^ ((bc_row & 7) << 4)) + klow;
                *reinterpret_cast<__half*>(pB + offh) = hh;
                *reinterpret_cast<__half*>(pB + offc) = ch;
                __syncwarp();
            }
        }

        grid_sync(++q);   // single global barrier per step (B tiles + HC visible)
    }

    asm volatile("cp.async.wait_group 0;" ::: "memory");

    // ---- final projection for own nodes ----
    if (tid < 32) {
        const int n = bid * 32 + tid;
        float s = b_fc[0];
        #pragma unroll
        for (int u = 0; u < HDIM; u++) s += g_HC[n * 64 + u] * W_fc[u];
        out[n] = s;
    }
}

// ---------------- launch --------------------------------------------------------
extern "C" void kernel_launch(void* const* d_in, const int* in_sizes, int n_in,
                              void* d_out, int out_size) {
    const float* X    = (const float*)d_in[0];
    const float* A    = (const float*)d_in[1];
    const float* Wx   = (const float*)d_in[2];
    const float* Wh   = (const float*)d_in[3];
    const float* Wc   = (const float*)d_in[4];
    const float* W_ih = (const float*)d_in[5];
    const float* W_hh = (const float*)d_in[6];
    const float* b_ih = (const float*)d_in[7];
    const float* b_hh = (const float*)d_in[8];
    const float* W_fc = (const float*)d_in[9];
    const float* b_fc = (const float*)d_in[10];

    cudaFuncSetAttribute(c1_mma, cudaFuncAttributeMaxDynamicSharedMemorySize, C1_SMEM);
    cudaFuncSetAttribute(fused_steps, cudaFuncAttributeMaxDynamicSharedMemorySize, FS_SMEM);

    setup_kernel<<<1, 128>>>(Wx, Wh, Wc, W_ih, W_hh, b_ih, b_hh);
    zero_state_kernel<<<(NN * 64) / 256, 256>>>();
    xrconv_kernel<<<(1024 * 512) / 256, 256>>>(X);
    aconv_kernel<<<(NN * 512) / 256, 256>>>(A);
    c1_mma<<<dim3(32, 16), 256, C1_SMEM>>>();
    fused_steps<<<NCTA, 256, FS_SMEM>>>(W_fc, b_fc, (float*)d_out);
}